// round 4
// baseline (speedup 1.0000x reference)
#include <cuda_runtime.h>

// db2 filter constants
#define DL0 (-0.12940952255092145f)
#define DL1 ( 0.22414386804185735f)
#define DL2 ( 0.836516303737469f)
#define DL3 ( 0.48296291314469025f)
#define DH0 (-0.48296291314469025f)
#define DH1 ( 0.836516303737469f)
#define DH2 (-0.22414386804185735f)
#define DH3 (-0.12940952255092145f)
#define RL0 ( 0.48296291314469025f)
#define RL1 ( 0.836516303737469f)
#define RL2 ( 0.22414386804185735f)
#define RL3 (-0.12940952255092145f)
#define RH0 (-0.12940952255092145f)
#define RH1 (-0.22414386804185735f)
#define RH2 ( 0.836516303737469f)
#define RH3 (-0.48296291314469025f)

static constexpr int D        = 512; // row length (floats)
static constexpr int WARPS_PB = 8;   // one row per warp
static constexpr int TPB      = WARPS_PB * 32;

// One warp per 512-float row. Lane L owns x[16L .. 16L+15] (4x LDG.128, MLP=4).
// Full stencil halo comes from 4 shuffles; row boundaries are register fixups
// on lanes 0/31 (symmetric extension). Zero extra global loads.
__global__ __launch_bounds__(TPB)
void wavelet_db2_row_kernel(const float* __restrict__ x,
                            const float* __restrict__ weight,
                            float* __restrict__ out)
{
    const int warp = threadIdx.x >> 5;
    const int lane = threadIdx.x & 31;

    const long long row = (long long)blockIdx.x * WARPS_PB + warp;
    const float* __restrict__ rowp = x + row * D;
    const int c = lane << 4;   // 16 * lane

    // ---- 4 independent coalesced LDG.128 (front-batched, MLP_p1 = 4) ----
    const float4 v0 = __ldcs(reinterpret_cast<const float4*>(rowp + c));
    const float4 v1 = __ldcs(reinterpret_cast<const float4*>(rowp + c + 4));
    const float4 v2 = __ldcs(reinterpret_cast<const float4*>(rowp + c + 8));
    const float4 v3 = __ldcs(reinterpret_cast<const float4*>(rowp + c + 12));

    // ---- halo via 4 shuffles (for 16 outputs) ----
    float xm2 = __shfl_up_sync(0xffffffffu, v3.z, 1);    // x[c-2]
    float xm1 = __shfl_up_sync(0xffffffffu, v3.w, 1);    // x[c-1]
    float xp0 = __shfl_down_sync(0xffffffffu, v0.x, 1);  // x[c+16]
    float xp1 = __shfl_down_sync(0xffffffffu, v0.y, 1);  // x[c+17]

    if (lane == 0)  { xm2 = v0.y; xm1 = v0.x; }          // x[1], x[0]
    if (lane == 31) { xp0 = v3.w; xp1 = v3.z; }          // x[511], x[510]

    // s[0..19] = x[c-2 .. c+17]
    const float s[20] = {xm2, xm1,
                         v0.x, v0.y, v0.z, v0.w,
                         v1.x, v1.y, v1.z, v1.w,
                         v2.x, v2.y, v2.z, v2.w,
                         v3.x, v3.y, v3.z, v3.w,
                         xp0, xp1};

    // ---- analysis: cA/cD at j = c/2 + i, i = 0..8 ----
    float cA[9], cD[9];
#pragma unroll
    for (int i = 0; i < 9; i++) {
        cA[i] = fmaf(s[2*i], DL3, fmaf(s[2*i+1], DL2, fmaf(s[2*i+2], DL1, s[2*i+3] * DL0)));
        cD[i] = fmaf(s[2*i], DH3, fmaf(s[2*i+1], DH2, fmaf(s[2*i+2], DH1, s[2*i+3] * DH0)));
    }

    // ---- detail scaling: weight row0[k .. k+8], k = 8*lane (16B aligned) ----
    const int k = lane << 3;
    const float4 wa = __ldg(reinterpret_cast<const float4*>(weight + k));
    const float4 wb = __ldg(reinterpret_cast<const float4*>(weight + k + 4));
    const float  w8 = __ldg(weight + k + 8);
    cD[0] *= wa.x; cD[1] *= wa.y; cD[2] *= wa.z; cD[3] *= wa.w;
    cD[4] *= wb.x; cD[5] *= wb.y; cD[6] *= wb.z; cD[7] *= wb.w;
    cD[8] *= w8;

    // ---- synthesis + leaky ReLU, 4x STG.128 ----
    float* op = out + row * D + c;
#pragma unroll
    for (int q = 0; q < 4; q++) {
        float4 z;
        const int i = 2 * q;
        float ze = fmaf(RL2, cA[i],   fmaf(RL0, cA[i+1], fmaf(RH2, cD[i],   RH0 * cD[i+1])));
        float zo = fmaf(RL3, cA[i],   fmaf(RL1, cA[i+1], fmaf(RH3, cD[i],   RH1 * cD[i+1])));
        z.x = ze > 0.0f ? ze : 0.01f * ze;
        z.y = zo > 0.0f ? zo : 0.01f * zo;
        ze = fmaf(RL2, cA[i+1], fmaf(RL0, cA[i+2], fmaf(RH2, cD[i+1], RH0 * cD[i+2])));
        zo = fmaf(RL3, cA[i+1], fmaf(RL1, cA[i+2], fmaf(RH3, cD[i+1], RH1 * cD[i+2])));
        z.z = ze > 0.0f ? ze : 0.01f * ze;
        z.w = zo > 0.0f ? zo : 0.01f * zo;
        __stcs(reinterpret_cast<float4*>(op + 4 * q), z);
    }
}

extern "C" void kernel_launch(void* const* d_in, const int* in_sizes, int n_in,
                              void* d_out, int out_size)
{
    const float* x = (const float*)d_in[0];   // (B, 512) fp32
    const float* w = (const float*)d_in[1];   // (2, 257) fp32
    float* out = (float*)d_out;               // (B, 512) fp32

    const int nrows = in_sizes[0] / D;        // 65536
    const int grid  = nrows / WARPS_PB;       // 8192

    wavelet_db2_row_kernel<<<grid, TPB>>>(x, w, out);
}

// round 5
// speedup vs baseline: 1.2406x; 1.2406x over previous
#include <cuda_runtime.h>

// db2 filter constants
#define DL0 (-0.12940952255092145f)
#define DL1 ( 0.22414386804185735f)
#define DL2 ( 0.836516303737469f)
#define DL3 ( 0.48296291314469025f)
#define DH0 (-0.48296291314469025f)
#define DH1 ( 0.836516303737469f)
#define DH2 (-0.22414386804185735f)
#define DH3 (-0.12940952255092145f)
#define RL0 ( 0.48296291314469025f)
#define RL1 ( 0.836516303737469f)
#define RL2 ( 0.22414386804185735f)
#define RL3 (-0.12940952255092145f)
#define RH0 (-0.12940952255092145f)
#define RH1 (-0.22414386804185735f)
#define RH2 ( 0.836516303737469f)
#define RH3 (-0.48296291314469025f)

static constexpr int D        = 512;  // row length (floats)
static constexpr int WARPS_PB = 8;
static constexpr int TPB      = WARPS_PB * 32;
static constexpr unsigned FULL = 0xffffffffu;

// Given stencil window s[-2..5] around a quad (v = x[c..c+3], halo m2,m1,p4,p5),
// produce 4 outputs z[c..c+3] with detail-scaled synthesis + leaky ReLU.
__device__ __forceinline__ float4 quad_compute(float m2, float m1, float4 v,
                                               float p4, float p5,
                                               float w0, float w1, float w2)
{
    const float cA0 = fmaf(m2,  DL3, fmaf(m1,  DL2, fmaf(v.x, DL1, v.y * DL0)));
    const float cA1 = fmaf(v.x, DL3, fmaf(v.y, DL2, fmaf(v.z, DL1, v.w * DL0)));
    const float cA2 = fmaf(v.z, DL3, fmaf(v.w, DL2, fmaf(p4,  DL1, p5  * DL0)));

    float cD0 = fmaf(m2,  DH3, fmaf(m1,  DH2, fmaf(v.x, DH1, v.y * DH0)));
    float cD1 = fmaf(v.x, DH3, fmaf(v.y, DH2, fmaf(v.z, DH1, v.w * DH0)));
    float cD2 = fmaf(v.z, DH3, fmaf(v.w, DH2, fmaf(p4,  DH1, p5  * DH0)));
    cD0 *= w0; cD1 *= w1; cD2 *= w2;

    float4 z;
    z.x = fmaf(RL2, cA0, fmaf(RL0, cA1, fmaf(RH2, cD0, RH0 * cD1)));
    z.y = fmaf(RL3, cA0, fmaf(RL1, cA1, fmaf(RH3, cD0, RH1 * cD1)));
    z.z = fmaf(RL2, cA1, fmaf(RL0, cA2, fmaf(RH2, cD1, RH0 * cD2)));
    z.w = fmaf(RL3, cA1, fmaf(RL1, cA2, fmaf(RH3, cD1, RH1 * cD2)));
    z.x = z.x > 0.0f ? z.x : 0.01f * z.x;
    z.y = z.y > 0.0f ? z.y : 0.01f * z.y;
    z.z = z.z > 0.0f ? z.z : 0.01f * z.z;
    z.w = z.w > 0.0f ? z.w : 0.01f * z.w;
    return z;
}

// One warp per 256-float half-row, owned as TWO warp-contiguous chunks:
//   quad A: x[base + 4*lane .. +3]        (chunk covers base .. base+127)
//   quad B: x[base + 128 + 4*lane .. +3]  (chunk covers base+128 .. base+255)
// Every LDG.128 / STG.128 instruction is perfectly contiguous (4 cache lines).
// Halo: neighbor-lane shuffles inside each chunk; the A<->B seam uses two
// broadcast shuffles; segment/row boundaries use __ldg (L2 hit) / symmetric ext.
__global__ __launch_bounds__(TPB)
void wavelet_db2_2chunk_kernel(const float* __restrict__ x,
                               const float* __restrict__ weight,
                               float* __restrict__ out)
{
    const int warp = threadIdx.x >> 5;
    const int lane = threadIdx.x & 31;

    const long long chunk = (long long)blockIdx.x * WARPS_PB + warp;
    const long long row   = chunk >> 1;
    const int       seg   = (int)(chunk & 1);

    const float* __restrict__ rowp = x + row * D;
    const int base = seg << 8;              // 0 or 256
    const int offA = base + (lane << 2);    // quad A position
    const int offB = offA + 128;            // quad B position

    // ---- two independent, perfectly-coalesced LDG.128 ----
    const float4 vA = __ldcs(reinterpret_cast<const float4*>(rowp + offA));
    const float4 vB = __ldcs(reinterpret_cast<const float4*>(rowp + offB));

    // ---- halo for quad A ----
    float am2 = __shfl_up_sync(FULL, vA.z, 1);      // x[offA-2]
    float am1 = __shfl_up_sync(FULL, vA.w, 1);      // x[offA-1]
    float ap4 = __shfl_down_sync(FULL, vA.x, 1);    // x[offA+4]
    float ap5 = __shfl_down_sync(FULL, vA.y, 1);    // x[offA+5]
    const float b0x = __shfl_sync(FULL, vB.x, 0);   // x[base+128]
    const float b0y = __shfl_sync(FULL, vB.y, 0);   // x[base+129]
    if (lane == 0) {
        if (seg == 0) { am2 = vA.y; am1 = vA.x; }   // symmetric: x[1], x[0]
        else { am2 = __ldg(rowp + base - 2); am1 = __ldg(rowp + base - 1); }
    }
    if (lane == 31) { ap4 = b0x; ap5 = b0y; }       // seam into chunk B

    // ---- halo for quad B ----
    float bm2 = __shfl_up_sync(FULL, vB.z, 1);      // x[offB-2]
    float bm1 = __shfl_up_sync(FULL, vB.w, 1);      // x[offB-1]
    float bp4 = __shfl_down_sync(FULL, vB.x, 1);    // x[offB+4]
    float bp5 = __shfl_down_sync(FULL, vB.y, 1);    // x[offB+5]
    const float a31z = __shfl_sync(FULL, vA.z, 31); // x[base+126]
    const float a31w = __shfl_sync(FULL, vA.w, 31); // x[base+127]
    if (lane == 0)  { bm2 = a31z; bm1 = a31w; }     // seam from chunk A
    if (lane == 31) {
        if (seg == 1) { bp4 = vB.w; bp5 = vB.z; }   // symmetric: x[511], x[510]
        else { bp4 = __ldg(rowp + base + 256); bp5 = __ldg(rowp + base + 257); }
    }

    // ---- weights: quad A uses w[kA..kA+2], kA = base/2 + 2*lane (even) ----
    const int kA = (base >> 1) + (lane << 1);
    const float2 wA01 = __ldg(reinterpret_cast<const float2*>(weight) + (kA >> 1));
    const float  wA2  = __ldg(weight + kA + 2);
    const int kB = kA + 64;
    const float2 wB01 = __ldg(reinterpret_cast<const float2*>(weight) + (kB >> 1));
    const float  wB2  = __ldg(weight + kB + 2);

    // ---- compute + perfectly-coalesced stores ----
    const float4 zA = quad_compute(am2, am1, vA, ap4, ap5, wA01.x, wA01.y, wA2);
    const float4 zB = quad_compute(bm2, bm1, vB, bp4, bp5, wB01.x, wB01.y, wB2);

    float* op = out + row * D;
    __stcs(reinterpret_cast<float4*>(op + offA), zA);
    __stcs(reinterpret_cast<float4*>(op + offB), zB);
}

extern "C" void kernel_launch(void* const* d_in, const int* in_sizes, int n_in,
                              void* d_out, int out_size)
{
    const float* x = (const float*)d_in[0];   // (B, 512) fp32
    const float* w = (const float*)d_in[1];   // (2, 257) fp32
    float* out = (float*)d_out;               // (B, 512) fp32

    const int nrows = in_sizes[0] / D;                 // 65536
    const long long chunks = (long long)nrows * 2;     // 131072 half-rows
    const int grid = (int)(chunks / WARPS_PB);         // 16384

    wavelet_db2_2chunk_kernel<<<grid, TPB>>>(x, w, out);
}